// round 1
// baseline (speedup 1.0000x reference)
#include <cuda_runtime.h>

#define HID 128
#define LAT 256
#define NN  1024

// ---------------- scratch (no allocations allowed) ----------------
__device__ float d_gvec[HID];            // nr_b1 + g @ nr_w1[:,128:]^T
__device__ float d_w1hT[HID * HID];      // [c][k] = nr_w1[k][c]      (node half)
__device__ float d_w2T [HID * HID];      // [k][j] = nr_w2[j][k]
__device__ float d_WaT [HID * HID];      // [k][j] = em_w1[j][k]
__device__ float d_WbT [HID * HID];      // [k][j] = em_w1[j][128+k]
__device__ float d_piT [HID * NN];       // [h][i] = pi[i][h]
__device__ float d_pbT [HID * NN];       // [h][j] = pj[j][h] + em_b1[h]

__device__ __forceinline__ float warp_sum(float v) {
#pragma unroll
    for (int o = 16; o; o >>= 1) v += __shfl_xor_sync(0xffffffffu, v, o);
    return v;
}

// ---------------- kernel A: latent decoder + global-feat folding ----------------
// h = LN(z @ ld_w1^T + b1); g = relu(h) @ ld_w2^T + b2
// d_gvec[k] = nr_b1[k] + sum_c g[c] * nr_w1[k][128+c]
__global__ __launch_bounds__(256) void kA(
    const float* __restrict__ z,
    const float* __restrict__ ld_w1, const float* __restrict__ ld_b1,
    const float* __restrict__ ld_g,  const float* __restrict__ ld_be,
    const float* __restrict__ ld_w2, const float* __restrict__ ld_b2,
    const float* __restrict__ nr_w1, const float* __restrict__ nr_b1)
{
    __shared__ float z_s[LAT], h_s[LAT], a_s[LAT], g_s[HID];
    __shared__ float redA[8], redB[8];
    const int t = threadIdx.x, w = t >> 5, l = t & 31;

    if (t < LAT) z_s[t] = z[t];
    __syncthreads();

    // rows of ld_w1 (256 x 256): warp per row, lanes along c (coalesced)
    for (int r = w; r < LAT; r += 8) {
        float p = 0.f;
#pragma unroll
        for (int m = 0; m < 8; m++) {
            int c = l + 32 * m;
            p += z_s[c] * ld_w1[r * LAT + c];
        }
        p = warp_sum(p);
        if (l == 0) h_s[r] = p + ld_b1[r];
    }
    __syncthreads();

    // LayerNorm over 256
    float x = h_s[t];
    float s1 = warp_sum(x), s2 = warp_sum(x * x);
    if (l == 0) { redA[w] = s1; redB[w] = s2; }
    __syncthreads();
    float tot = 0.f, tot2 = 0.f;
#pragma unroll
    for (int i = 0; i < 8; i++) { tot += redA[i]; tot2 += redB[i]; }
    float mu = tot * (1.f / 256.f);
    float var = tot2 * (1.f / 256.f) - mu * mu;
    float rs = rsqrtf(var + 1e-5f);
    a_s[t] = fmaxf((x - mu) * rs * ld_g[t] + ld_be[t], 0.f);
    __syncthreads();

    // g = relu(ln) @ ld_w2^T + b2   (128 rows, 256 dot)
    for (int r = w; r < HID; r += 8) {
        float p = 0.f;
#pragma unroll
        for (int m = 0; m < 8; m++) {
            int c = l + 32 * m;
            p += a_s[c] * ld_w2[r * LAT + c];
        }
        p = warp_sum(p);
        if (l == 0) g_s[r] = p + ld_b2[r];
    }
    __syncthreads();

    // gvec[k] = nr_b1[k] + sum_c g[c] * nr_w1[k][128+c]
    for (int r = w; r < HID; r += 8) {
        float p = 0.f;
#pragma unroll
        for (int m = 0; m < 4; m++) {
            int c = l + 32 * m;
            p += g_s[c] * nr_w1[r * LAT + HID + c];
        }
        p = warp_sum(p);
        if (l == 0) d_gvec[r] = p + nr_b1[r];
    }
}

// ---------------- kernel T: weight transposes ----------------
__global__ void kT(const float* __restrict__ nr_w1,
                   const float* __restrict__ nr_w2,
                   const float* __restrict__ em_w1)
{
    const int c = blockIdx.x;    // 0..127 (output-major index)
    const int k = threadIdx.x;   // 0..127
    d_w1hT[c * HID + k] = nr_w1[k * LAT + c];
    d_w2T [c * HID + k] = nr_w2[k * HID + c];
    d_WaT [c * HID + k] = em_w1[k * LAT + c];
    d_WbT [c * HID + k] = em_w1[k * LAT + HID + c];
}

// ---------------- kernel B: fused node MLP -> piT / pjbT ----------------
// per row i: h1 = ne_i @ w1h^T + gvec; a = relu(LN(h1)); nf = a @ nr_w2^T + b2;
// pi = nf @ Wa^T; pjb = nf @ Wb^T + em_b1   -> stored transposed (h-major)
__global__ __launch_bounds__(256) void kB(
    const float* __restrict__ ne,
    const float* __restrict__ nr_g, const float* __restrict__ nr_be,
    const float* __restrict__ nr_b2, const float* __restrict__ em_b1)
{
    __shared__ float ne_s[8 * HID], h_s[8 * HID], nf_s[8 * HID];
    __shared__ float pis[8 * HID], pbs[8 * HID];
    const int t = threadIdx.x;
    const int i0 = blockIdx.x * 8;
    const int r = t >> 5;           // row within block (0..7), warp-uniform
    const int l = t & 31;
    const int j4 = l * 4;

    for (int q = t; q < 8 * HID; q += 256) ne_s[q] = ne[i0 * HID + q];
    __syncthreads();

    // phase 1: h1
    float a0 = d_gvec[j4], a1 = d_gvec[j4 + 1], a2 = d_gvec[j4 + 2], a3 = d_gvec[j4 + 3];
#pragma unroll 8
    for (int c = 0; c < HID; c++) {
        float nec = ne_s[r * HID + c];
        float4 wv = *(const float4*)&d_w1hT[c * HID + j4];
        a0 = fmaf(nec, wv.x, a0); a1 = fmaf(nec, wv.y, a1);
        a2 = fmaf(nec, wv.z, a2); a3 = fmaf(nec, wv.w, a3);
    }
    *(float4*)&h_s[r * HID + j4] = make_float4(a0, a1, a2, a3);
    __syncthreads();

    // phase 2: LayerNorm(128) + relu  (warp r handles row r)
    {
        float xs[4], s1 = 0.f, s2 = 0.f;
#pragma unroll
        for (int m = 0; m < 4; m++) {
            xs[m] = h_s[r * HID + l + 32 * m];
            s1 += xs[m]; s2 += xs[m] * xs[m];
        }
        s1 = warp_sum(s1); s2 = warp_sum(s2);
        float mu = s1 * (1.f / 128.f);
        float var = s2 * (1.f / 128.f) - mu * mu;
        float rs = rsqrtf(var + 1e-5f);
#pragma unroll
        for (int m = 0; m < 4; m++) {
            int c = l + 32 * m;
            h_s[r * HID + c] = fmaxf((xs[m] - mu) * rs * nr_g[c] + nr_be[c], 0.f);
        }
    }
    __syncthreads();

    // phase 3: nf
    float n0 = nr_b2[j4], n1 = nr_b2[j4 + 1], n2 = nr_b2[j4 + 2], n3 = nr_b2[j4 + 3];
#pragma unroll 8
    for (int c = 0; c < HID; c++) {
        float ac = h_s[r * HID + c];
        float4 wv = *(const float4*)&d_w2T[c * HID + j4];
        n0 = fmaf(ac, wv.x, n0); n1 = fmaf(ac, wv.y, n1);
        n2 = fmaf(ac, wv.z, n2); n3 = fmaf(ac, wv.w, n3);
    }
    *(float4*)&nf_s[r * HID + j4] = make_float4(n0, n1, n2, n3);
    __syncthreads();

    // phase 4: pi and pjb
    float p0 = 0.f, p1 = 0.f, p2 = 0.f, p3 = 0.f;
    float q0 = em_b1[j4], q1 = em_b1[j4 + 1], q2 = em_b1[j4 + 2], q3 = em_b1[j4 + 3];
#pragma unroll 4
    for (int c = 0; c < HID; c++) {
        float nfc = nf_s[r * HID + c];
        float4 wa = *(const float4*)&d_WaT[c * HID + j4];
        float4 wb = *(const float4*)&d_WbT[c * HID + j4];
        p0 = fmaf(nfc, wa.x, p0); p1 = fmaf(nfc, wa.y, p1);
        p2 = fmaf(nfc, wa.z, p2); p3 = fmaf(nfc, wa.w, p3);
        q0 = fmaf(nfc, wb.x, q0); q1 = fmaf(nfc, wb.y, q1);
        q2 = fmaf(nfc, wb.z, q2); q3 = fmaf(nfc, wb.w, q3);
    }
    *(float4*)&pis[r * HID + j4] = make_float4(p0, p1, p2, p3);
    *(float4*)&pbs[r * HID + j4] = make_float4(q0, q1, q2, q3);
    __syncthreads();

    // writeback transposed: d_piT[j][i0..i0+7]
    if (t < HID) {
        const int j = t;
        float4 lo = make_float4(pis[0 * HID + j], pis[1 * HID + j], pis[2 * HID + j], pis[3 * HID + j]);
        float4 hi = make_float4(pis[4 * HID + j], pis[5 * HID + j], pis[6 * HID + j], pis[7 * HID + j]);
        *(float4*)&d_piT[j * NN + i0]     = lo;
        *(float4*)&d_piT[j * NN + i0 + 4] = hi;
        float4 lo2 = make_float4(pbs[0 * HID + j], pbs[1 * HID + j], pbs[2 * HID + j], pbs[3 * HID + j]);
        float4 hi2 = make_float4(pbs[4 * HID + j], pbs[5 * HID + j], pbs[6 * HID + j], pbs[7 * HID + j]);
        *(float4*)&d_pbT[j * NN + i0]     = lo2;
        *(float4*)&d_pbT[j * NN + i0 + 4] = hi2;
    }
}

// ---------------- kernel C: edge scores ----------------
// out[i][j] = sigmoid( sum_h w[h]*relu(pi[i][h]+pjb[j][h]) + b2 )
// 64x64 block tile, 4x4 per thread, h chunked by 64 (32 KB smem resident)
__global__ __launch_bounds__(256) void kC(
    const float* __restrict__ em_w2, const float* __restrict__ em_b2,
    float* __restrict__ out)
{
    __shared__ float pi_s[64 * 64];   // [h_local][i]
    __shared__ float pb_s[64 * 64];   // [h_local][j]
    __shared__ float w_s[HID];
    const int t = threadIdx.x;
    const int tx = t & 15, ty = t >> 4;
    const int i0 = blockIdx.y * 64, j0 = blockIdx.x * 64;

    if (t < HID) w_s[t] = em_w2[t];

    float acc[4][4] = {};

#pragma unroll
    for (int ch = 0; ch < 2; ch++) {
        __syncthreads();
        const int h0 = ch * 64;
        for (int q = t; q < 64 * 16; q += 256) {
            int hl = q >> 4, i4 = (q & 15) * 4;
            *(float4*)&pi_s[hl * 64 + i4] = *(const float4*)&d_piT[(h0 + hl) * NN + i0 + i4];
            *(float4*)&pb_s[hl * 64 + i4] = *(const float4*)&d_pbT[(h0 + hl) * NN + j0 + i4];
        }
        __syncthreads();

#pragma unroll 8
        for (int hl = 0; hl < 64; hl++) {
            float4 pv = *(const float4*)&pi_s[hl * 64 + ty * 4];
            float4 qv = *(const float4*)&pb_s[hl * 64 + tx * 4];
            float wh = w_s[h0 + hl];
            float pa[4] = {pv.x, pv.y, pv.z, pv.w};
            float qa[4] = {qv.x, qv.y, qv.z, qv.w};
#pragma unroll
            for (int a = 0; a < 4; a++)
#pragma unroll
                for (int b = 0; b < 4; b++) {
                    float v = fmaxf(pa[a] + qa[b], 0.f);
                    acc[a][b] = fmaf(v, wh, acc[a][b]);
                }
        }
    }

    const float b2 = em_b2[0];
#pragma unroll
    for (int a = 0; a < 4; a++) {
        float4 o;
        o.x = 1.f / (1.f + __expf(-(acc[a][0] + b2)));
        o.y = 1.f / (1.f + __expf(-(acc[a][1] + b2)));
        o.z = 1.f / (1.f + __expf(-(acc[a][2] + b2)));
        o.w = 1.f / (1.f + __expf(-(acc[a][3] + b2)));
        *(float4*)&out[(i0 + ty * 4 + a) * NN + j0 + tx * 4] = o;
    }
}

// ---------------- kernel D: in-place symmetrize ----------------
__global__ void kD(float* __restrict__ out)
{
    const int bx = blockIdx.x, by = blockIdx.y;
    if (by > bx) return;                 // one block per unordered tile pair
    __shared__ float A[32][33], B[32][33];
    const int x = threadIdx.x, y = threadIdx.y;
    const int iA = by * 32 + y, jA = bx * 32 + x;   // tile (by,bx)
    const int iB = bx * 32 + y, jB = by * 32 + x;   // tile (bx,by)
    A[y][x] = out[iA * NN + jA];
    B[y][x] = out[iB * NN + jB];
    __syncthreads();
    out[iA * NN + jA] = 0.5f * (A[y][x] + B[x][y]);
    out[iB * NN + jB] = 0.5f * (B[y][x] + A[x][y]);
}

// ---------------- launch ----------------
extern "C" void kernel_launch(void* const* d_in, const int* in_sizes, int n_in,
                              void* d_out, int out_size)
{
    // Defensive index mapping: num_nodes (scalar, size 1) may or may not be input #2.
    const int o = (n_in >= 19 && in_sizes[2] == 1) ? 1 : 0;
    const float* z     = (const float*)d_in[0];
    const float* ne    = (const float*)d_in[1];
    const float* ld_w1 = (const float*)d_in[2 + o];
    const float* ld_b1 = (const float*)d_in[3 + o];
    const float* ld_g  = (const float*)d_in[4 + o];
    const float* ld_be = (const float*)d_in[5 + o];
    const float* ld_w2 = (const float*)d_in[6 + o];
    const float* ld_b2 = (const float*)d_in[7 + o];
    const float* nr_w1 = (const float*)d_in[8 + o];
    const float* nr_b1 = (const float*)d_in[9 + o];
    const float* nr_g  = (const float*)d_in[10 + o];
    const float* nr_be = (const float*)d_in[11 + o];
    const float* nr_w2 = (const float*)d_in[12 + o];
    const float* nr_b2 = (const float*)d_in[13 + o];
    const float* em_w1 = (const float*)d_in[14 + o];
    const float* em_b1 = (const float*)d_in[15 + o];
    const float* em_w2 = (const float*)d_in[16 + o];
    const float* em_b2 = (const float*)d_in[17 + o];
    float* out = (float*)d_out;

    kA<<<1, 256>>>(z, ld_w1, ld_b1, ld_g, ld_be, ld_w2, ld_b2, nr_w1, nr_b1);
    kT<<<128, 128>>>(nr_w1, nr_w2, em_w1);
    kB<<<128, 256>>>(ne, nr_g, nr_be, nr_b2, em_b1);
    kC<<<dim3(16, 16), 256>>>(em_w2, em_b2, out);
    kD<<<dim3(32, 32), dim3(32, 32)>>>(out);
}

// round 2
// speedup vs baseline: 1.2407x; 1.2407x over previous
#include <cuda_runtime.h>

#define HID 128
#define LAT 256
#define NN  1024

// ---------------- scratch (no allocations allowed) ----------------
__device__ float d_gvec[HID];            // nr_b1 + g @ nr_w1[:,128:]^T
__device__ float d_w1hT[HID * HID];      // [c][k] = nr_w1[k][c]      (node half)
__device__ float d_w2T [HID * HID];      // [k][j] = nr_w2[j][k]
__device__ float d_WaT [HID * HID];      // [k][j] = em_w1[j][k]
__device__ float d_WbT [HID * HID];      // [k][j] = em_w1[j][128+k]
__device__ float d_piT [HID * NN];       // [h][i] = pi[i][h]
__device__ float d_pbT [HID * NN];       // [h][j] = pj[j][h] + em_b1[h]

__device__ __forceinline__ float warp_sum(float v) {
#pragma unroll
    for (int o = 16; o; o >>= 1) v += __shfl_xor_sync(0xffffffffu, v, o);
    return v;
}

// packed f32x2 helpers (Blackwell FADD2 / FFMA2)
__device__ __forceinline__ float2 f2add(float2 a, float2 b) {
    unsigned long long ua = *reinterpret_cast<unsigned long long*>(&a);
    unsigned long long ub = *reinterpret_cast<unsigned long long*>(&b);
    unsigned long long ur;
    asm("add.rn.f32x2 %0, %1, %2;" : "=l"(ur) : "l"(ua), "l"(ub));
    return *reinterpret_cast<float2*>(&ur);
}
__device__ __forceinline__ float2 f2fma(float2 a, float2 b, float2 c) {
    unsigned long long ua = *reinterpret_cast<unsigned long long*>(&a);
    unsigned long long ub = *reinterpret_cast<unsigned long long*>(&b);
    unsigned long long uc = *reinterpret_cast<unsigned long long*>(&c);
    unsigned long long ur;
    asm("fma.rn.f32x2 %0, %1, %2, %3;" : "=l"(ur) : "l"(ua), "l"(ub), "l"(uc));
    return *reinterpret_cast<float2*>(&ur);
}

__device__ __forceinline__ float sigm(float x) { return 1.f / (1.f + __expf(-x)); }

// ---------------- kernel AT: block 0 = latent chain; blocks 1..64 = transposes ----------------
__global__ __launch_bounds__(256) void kAT(
    const float* __restrict__ z,
    const float* __restrict__ ld_w1, const float* __restrict__ ld_b1,
    const float* __restrict__ ld_g,  const float* __restrict__ ld_be,
    const float* __restrict__ ld_w2, const float* __restrict__ ld_b2,
    const float* __restrict__ nr_w1, const float* __restrict__ nr_b1,
    const float* __restrict__ nr_w2, const float* __restrict__ em_w1)
{
    const int t = threadIdx.x;

    if (blockIdx.x != 0) {
        // ---- tiled transposes: dst[c][k] = src[k*stride + colOff + c] ----
        __shared__ float s[32][33];
        const int tileIdx = blockIdx.x - 1;        // 0..63
        const int m  = tileIdx >> 4;               // matrix 0..3
        const int t16 = tileIdx & 15;
        const int c0 = (t16 >> 2) * 32;            // dst row block (c)
        const int k0 = (t16 & 3) * 32;             // dst col block (k)
        const float* src; int stride, colOff; float* dst;
        if      (m == 0) { src = nr_w1; stride = LAT; colOff = 0;   dst = d_w1hT; }
        else if (m == 1) { src = nr_w2; stride = HID; colOff = 0;   dst = d_w2T;  }
        else if (m == 2) { src = em_w1; stride = LAT; colOff = 0;   dst = d_WaT;  }
        else             { src = em_w1; stride = LAT; colOff = HID; dst = d_WbT;  }
        const int x = t & 31, y = t >> 5;          // 32 x 8
#pragma unroll
        for (int yy = y; yy < 32; yy += 8)
            s[yy][x] = src[(k0 + yy) * stride + colOff + c0 + x];
        __syncthreads();
#pragma unroll
        for (int yy = y; yy < 32; yy += 8)
            dst[(c0 + yy) * HID + k0 + x] = s[x][yy];
        return;
    }

    // ---- latent decoder chain (block 0) ----
    __shared__ float z_s[LAT], h_s[LAT], a_s[LAT], g_s[HID];
    __shared__ float redA[8], redB[8];
    const int w = t >> 5, l = t & 31;

    if (t < LAT) z_s[t] = z[t];
    __syncthreads();
    const float4* zf4 = (const float4*)z_s;

    // phase 1: h = z @ ld_w1^T + b1  (256 rows, dot 256); 4 rows per warp-group
    for (int m0 = 0; m0 < 32; m0 += 4) {
        float p[4];
#pragma unroll
        for (int jj = 0; jj < 4; jj++) {
            int r = w + 8 * (m0 + jj);
            const float4* wr = (const float4*)&ld_w1[r * LAT];
            float4 A = wr[l], B = wr[l + 32];
            float4 za = zf4[l], zb = zf4[l + 32];
            p[jj] = A.x*za.x + A.y*za.y + A.z*za.z + A.w*za.w
                  + B.x*zb.x + B.y*zb.y + B.z*zb.z + B.w*zb.w;
        }
#pragma unroll
        for (int o = 16; o; o >>= 1) {
            p[0] += __shfl_xor_sync(0xffffffffu, p[0], o);
            p[1] += __shfl_xor_sync(0xffffffffu, p[1], o);
            p[2] += __shfl_xor_sync(0xffffffffu, p[2], o);
            p[3] += __shfl_xor_sync(0xffffffffu, p[3], o);
        }
        if (l == 0) {
#pragma unroll
            for (int jj = 0; jj < 4; jj++) {
                int r = w + 8 * (m0 + jj);
                h_s[r] = p[jj] + ld_b1[r];
            }
        }
    }
    __syncthreads();

    // LayerNorm over 256 + relu
    {
        float x = h_s[t];
        float s1 = warp_sum(x), s2 = warp_sum(x * x);
        if (l == 0) { redA[w] = s1; redB[w] = s2; }
        __syncthreads();
        float tot = 0.f, tot2 = 0.f;
#pragma unroll
        for (int i = 0; i < 8; i++) { tot += redA[i]; tot2 += redB[i]; }
        float mu = tot * (1.f / 256.f);
        float var = tot2 * (1.f / 256.f) - mu * mu;
        float rs = rsqrtf(var + 1e-5f);
        a_s[t] = fmaxf((x - mu) * rs * ld_g[t] + ld_be[t], 0.f);
    }
    __syncthreads();
    const float4* af4 = (const float4*)a_s;

    // phase 2: g = relu(ln) @ ld_w2^T + b2  (128 rows, dot 256)
    for (int m0 = 0; m0 < 16; m0 += 4) {
        float p[4];
#pragma unroll
        for (int jj = 0; jj < 4; jj++) {
            int r = w + 8 * (m0 + jj);
            const float4* wr = (const float4*)&ld_w2[r * LAT];
            float4 A = wr[l], B = wr[l + 32];
            float4 za = af4[l], zb = af4[l + 32];
            p[jj] = A.x*za.x + A.y*za.y + A.z*za.z + A.w*za.w
                  + B.x*zb.x + B.y*zb.y + B.z*zb.z + B.w*zb.w;
        }
#pragma unroll
        for (int o = 16; o; o >>= 1) {
            p[0] += __shfl_xor_sync(0xffffffffu, p[0], o);
            p[1] += __shfl_xor_sync(0xffffffffu, p[1], o);
            p[2] += __shfl_xor_sync(0xffffffffu, p[2], o);
            p[3] += __shfl_xor_sync(0xffffffffu, p[3], o);
        }
        if (l == 0) {
#pragma unroll
            for (int jj = 0; jj < 4; jj++) {
                int r = w + 8 * (m0 + jj);
                g_s[r] = p[jj] + ld_b2[r];
            }
        }
    }
    __syncthreads();
    const float4* gf4 = (const float4*)g_s;

    // phase 3: gvec[k] = nr_b1[k] + sum_c g[c] * nr_w1[k][128+c]  (128 rows, dot 128)
    for (int m0 = 0; m0 < 16; m0 += 4) {
        float p[4];
#pragma unroll
        for (int jj = 0; jj < 4; jj++) {
            int r = w + 8 * (m0 + jj);
            const float4* wr = (const float4*)&nr_w1[r * LAT + HID];
            float4 A = wr[l];
            float4 ga = gf4[l];
            p[jj] = A.x*ga.x + A.y*ga.y + A.z*ga.z + A.w*ga.w;
        }
#pragma unroll
        for (int o = 16; o; o >>= 1) {
            p[0] += __shfl_xor_sync(0xffffffffu, p[0], o);
            p[1] += __shfl_xor_sync(0xffffffffu, p[1], o);
            p[2] += __shfl_xor_sync(0xffffffffu, p[2], o);
            p[3] += __shfl_xor_sync(0xffffffffu, p[3], o);
        }
        if (l == 0) {
#pragma unroll
            for (int jj = 0; jj < 4; jj++) {
                int r = w + 8 * (m0 + jj);
                d_gvec[r] = p[jj] + nr_b1[r];
            }
        }
    }
}

// ---------------- kernel B: fused node MLP -> piT / pjbT ----------------
__global__ __launch_bounds__(256) void kB(
    const float* __restrict__ ne,
    const float* __restrict__ nr_g, const float* __restrict__ nr_be,
    const float* __restrict__ nr_b2, const float* __restrict__ em_b1)
{
    __shared__ float ne_s[8 * HID], h_s[8 * HID], nf_s[8 * HID];
    __shared__ float pis[8 * HID], pbs[8 * HID];
    const int t = threadIdx.x;
    const int i0 = blockIdx.x * 8;
    const int r = t >> 5;
    const int l = t & 31;
    const int j4 = l * 4;

    for (int q = t; q < 8 * HID; q += 256) ne_s[q] = ne[i0 * HID + q];
    __syncthreads();

    // phase 1: h1 = ne_i @ w1h^T + gvec
    float a0 = d_gvec[j4], a1 = d_gvec[j4 + 1], a2 = d_gvec[j4 + 2], a3 = d_gvec[j4 + 3];
#pragma unroll 8
    for (int c = 0; c < HID; c++) {
        float nec = ne_s[r * HID + c];
        float4 wv = *(const float4*)&d_w1hT[c * HID + j4];
        a0 = fmaf(nec, wv.x, a0); a1 = fmaf(nec, wv.y, a1);
        a2 = fmaf(nec, wv.z, a2); a3 = fmaf(nec, wv.w, a3);
    }
    *(float4*)&h_s[r * HID + j4] = make_float4(a0, a1, a2, a3);
    __syncthreads();

    // phase 2: LayerNorm(128) + relu
    {
        float xs[4], s1 = 0.f, s2 = 0.f;
#pragma unroll
        for (int m = 0; m < 4; m++) {
            xs[m] = h_s[r * HID + l + 32 * m];
            s1 += xs[m]; s2 += xs[m] * xs[m];
        }
        s1 = warp_sum(s1); s2 = warp_sum(s2);
        float mu = s1 * (1.f / 128.f);
        float var = s2 * (1.f / 128.f) - mu * mu;
        float rs = rsqrtf(var + 1e-5f);
#pragma unroll
        for (int m = 0; m < 4; m++) {
            int c = l + 32 * m;
            h_s[r * HID + c] = fmaxf((xs[m] - mu) * rs * nr_g[c] + nr_be[c], 0.f);
        }
    }
    __syncthreads();

    // phase 3: nf = a @ nr_w2^T + b2
    float n0 = nr_b2[j4], n1 = nr_b2[j4 + 1], n2 = nr_b2[j4 + 2], n3 = nr_b2[j4 + 3];
#pragma unroll 8
    for (int c = 0; c < HID; c++) {
        float ac = h_s[r * HID + c];
        float4 wv = *(const float4*)&d_w2T[c * HID + j4];
        n0 = fmaf(ac, wv.x, n0); n1 = fmaf(ac, wv.y, n1);
        n2 = fmaf(ac, wv.z, n2); n3 = fmaf(ac, wv.w, n3);
    }
    *(float4*)&nf_s[r * HID + j4] = make_float4(n0, n1, n2, n3);
    __syncthreads();

    // phase 4: pi and pjb
    float p0 = 0.f, p1 = 0.f, p2 = 0.f, p3 = 0.f;
    float q0 = em_b1[j4], q1 = em_b1[j4 + 1], q2 = em_b1[j4 + 2], q3 = em_b1[j4 + 3];
#pragma unroll 4
    for (int c = 0; c < HID; c++) {
        float nfc = nf_s[r * HID + c];
        float4 wa = *(const float4*)&d_WaT[c * HID + j4];
        float4 wb = *(const float4*)&d_WbT[c * HID + j4];
        p0 = fmaf(nfc, wa.x, p0); p1 = fmaf(nfc, wa.y, p1);
        p2 = fmaf(nfc, wa.z, p2); p3 = fmaf(nfc, wa.w, p3);
        q0 = fmaf(nfc, wb.x, q0); q1 = fmaf(nfc, wb.y, q1);
        q2 = fmaf(nfc, wb.z, q2); q3 = fmaf(nfc, wb.w, q3);
    }
    *(float4*)&pis[r * HID + j4] = make_float4(p0, p1, p2, p3);
    *(float4*)&pbs[r * HID + j4] = make_float4(q0, q1, q2, q3);
    __syncthreads();

    if (t < HID) {
        const int j = t;
        float4 lo = make_float4(pis[0 * HID + j], pis[1 * HID + j], pis[2 * HID + j], pis[3 * HID + j]);
        float4 hi = make_float4(pis[4 * HID + j], pis[5 * HID + j], pis[6 * HID + j], pis[7 * HID + j]);
        *(float4*)&d_piT[j * NN + i0]     = lo;
        *(float4*)&d_piT[j * NN + i0 + 4] = hi;
        float4 lo2 = make_float4(pbs[0 * HID + j], pbs[1 * HID + j], pbs[2 * HID + j], pbs[3 * HID + j]);
        float4 hi2 = make_float4(pbs[4 * HID + j], pbs[5 * HID + j], pbs[6 * HID + j], pbs[7 * HID + j]);
        *(float4*)&d_pbT[j * NN + i0]     = lo2;
        *(float4*)&d_pbT[j * NN + i0 + 4] = hi2;
    }
}

// ---------------- kernel E: edge scores + fused symmetrize ----------------
// block handles unordered tile pair (bi,bj), bj>=bi:
//   E1[a][b]  = sum_h w[h]*relu(piT[h][I_a] + pbT[h][J_b])       (tile I,J)
//   E2t[a][b] = sum_h w[h]*relu(piT[h][J_b] + pbT[h][I_a])       (tile J,I, transposed)
//   out[I_a][J_b] = out-mirror = 0.5*(sigm(E1)+sigm(E2t))
__global__ __launch_bounds__(256) void kE(
    const float* __restrict__ em_w2, const float* __restrict__ em_b2,
    float* __restrict__ out)
{
    __shared__ float pool[4 * 32 * 64];   // 32 KB: 4 tiles of [32][64]; reused as ov[64][65] (16.25KB)
    __shared__ float w_s[HID];

    float (*piI)[64] = (float(*)[64])(pool);
    float (*pbJ)[64] = (float(*)[64])(pool + 2048);
    float (*piJ)[64] = (float(*)[64])(pool + 4096);
    float (*pbI)[64] = (float(*)[64])(pool + 6144);

    const int t = threadIdx.x;
    const int tx = t & 15, ty = t >> 4;
    const int ty4 = ty * 4, tx4 = tx * 4;

    // map linear block -> upper-triangle pair (bi, bj)
    int b = blockIdx.x, bi = 0;
    while (b >= (16 - bi)) { b -= (16 - bi); bi++; }
    const int bj = bi + b;
    const int i0 = bi * 64, j0 = bj * 64;

    if (t < HID) w_s[t] = em_w2[t];

    float2 acc1[4][2] = {};
    float2 acc2[4][2] = {};

#pragma unroll
    for (int ch = 0; ch < 4; ch++) {
        __syncthreads();
        const int h0 = ch * 32;
#pragma unroll
        for (int q = t; q < 32 * 16; q += 256) {
            int hl = q >> 4, c4 = (q & 15) * 4;
            *(float4*)&piI[hl][c4] = *(const float4*)&d_piT[(h0 + hl) * NN + i0 + c4];
            *(float4*)&pbJ[hl][c4] = *(const float4*)&d_pbT[(h0 + hl) * NN + j0 + c4];
            *(float4*)&piJ[hl][c4] = *(const float4*)&d_piT[(h0 + hl) * NN + j0 + c4];
            *(float4*)&pbI[hl][c4] = *(const float4*)&d_pbT[(h0 + hl) * NN + i0 + c4];
        }
        __syncthreads();

#pragma unroll 8
        for (int hl = 0; hl < 32; hl++) {
            float4 pI = *(const float4*)&piI[hl][ty4];
            float4 bI = *(const float4*)&pbI[hl][ty4];
            float4 pJ = *(const float4*)&piJ[hl][tx4];
            float4 bJ = *(const float4*)&pbJ[hl][tx4];
            float wh = w_s[h0 + hl];
            float2 w2 = make_float2(wh, wh);
            float2 q0 = make_float2(bJ.x, bJ.y), q1 = make_float2(bJ.z, bJ.w);
            float2 r0 = make_float2(pJ.x, pJ.y), r1 = make_float2(pJ.z, pJ.w);
            float pa[4] = {pI.x, pI.y, pI.z, pI.w};
            float ba[4] = {bI.x, bI.y, bI.z, bI.w};
#pragma unroll
            for (int a = 0; a < 4; a++) {
                float2 pp = make_float2(pa[a], pa[a]);
                float2 s0 = f2add(pp, q0);
                s0.x = fmaxf(s0.x, 0.f); s0.y = fmaxf(s0.y, 0.f);
                acc1[a][0] = f2fma(s0, w2, acc1[a][0]);
                float2 s1 = f2add(pp, q1);
                s1.x = fmaxf(s1.x, 0.f); s1.y = fmaxf(s1.y, 0.f);
                acc1[a][1] = f2fma(s1, w2, acc1[a][1]);

                float2 bb = make_float2(ba[a], ba[a]);
                float2 t0 = f2add(bb, r0);
                t0.x = fmaxf(t0.x, 0.f); t0.y = fmaxf(t0.y, 0.f);
                acc2[a][0] = f2fma(t0, w2, acc2[a][0]);
                float2 t1 = f2add(bb, r1);
                t1.x = fmaxf(t1.x, 0.f); t1.y = fmaxf(t1.y, 0.f);
                acc2[a][1] = f2fma(t1, w2, acc2[a][1]);
            }
        }
    }

    const float b2 = em_b2[0];
    __syncthreads();                       // tiles no longer needed; reuse pool as ov
    float (*ov)[65] = (float(*)[65])pool;  // wait: 64*65 = 4160 floats <= 8192, fits

    // compute symmetrized values, primary (I,J) write + stage for transposed write
#pragma unroll
    for (int a = 0; a < 4; a++) {
        float v0 = 0.5f * (sigm(acc1[a][0].x + b2) + sigm(acc2[a][0].x + b2));
        float v1 = 0.5f * (sigm(acc1[a][0].y + b2) + sigm(acc2[a][0].y + b2));
        float v2 = 0.5f * (sigm(acc1[a][1].x + b2) + sigm(acc2[a][1].x + b2));
        float v3 = 0.5f * (sigm(acc1[a][1].y + b2) + sigm(acc2[a][1].y + b2));
        *(float4*)&out[(i0 + ty4 + a) * NN + j0 + tx4] = make_float4(v0, v1, v2, v3);
        ov[ty4 + a][tx4]     = v0;
        ov[ty4 + a][tx4 + 1] = v1;
        ov[ty4 + a][tx4 + 2] = v2;
        ov[ty4 + a][tx4 + 3] = v3;
    }
    __syncthreads();

    // transposed write: out[(j0+r)][i0+c] = ov[c][r], coalesced over c
#pragma unroll
    for (int rb = 0; rb < 4; rb++) {
        int r = rb * 16 + ty;
        int c4 = tx4;
        float4 v = make_float4(ov[c4][r], ov[c4 + 1][r], ov[c4 + 2][r], ov[c4 + 3][r]);
        *(float4*)&out[(j0 + r) * NN + i0 + c4] = v;
    }
}

// ---------------- launch ----------------
extern "C" void kernel_launch(void* const* d_in, const int* in_sizes, int n_in,
                              void* d_out, int out_size)
{
    const int o = (n_in >= 19 && in_sizes[2] == 1) ? 1 : 0;
    const float* z     = (const float*)d_in[0];
    const float* ne    = (const float*)d_in[1];
    const float* ld_w1 = (const float*)d_in[2 + o];
    const float* ld_b1 = (const float*)d_in[3 + o];
    const float* ld_g  = (const float*)d_in[4 + o];
    const float* ld_be = (const float*)d_in[5 + o];
    const float* ld_w2 = (const float*)d_in[6 + o];
    const float* ld_b2 = (const float*)d_in[7 + o];
    const float* nr_w1 = (const float*)d_in[8 + o];
    const float* nr_b1 = (const float*)d_in[9 + o];
    const float* nr_g  = (const float*)d_in[10 + o];
    const float* nr_be = (const float*)d_in[11 + o];
    const float* nr_w2 = (const float*)d_in[12 + o];
    const float* nr_b2 = (const float*)d_in[13 + o];
    const float* em_w1 = (const float*)d_in[14 + o];
    const float* em_b1 = (const float*)d_in[15 + o];
    const float* em_w2 = (const float*)d_in[16 + o];
    const float* em_b2 = (const float*)d_in[17 + o];
    float* out = (float*)d_out;

    kAT<<<65, 256>>>(z, ld_w1, ld_b1, ld_g, ld_be, ld_w2, ld_b2, nr_w1, nr_b1, nr_w2, em_w1);
    kB<<<128, 256>>>(ne, nr_g, nr_be, nr_b2, em_b1);
    kE<<<136, 256>>>(em_w2, em_b2, out);
}

// round 3
// speedup vs baseline: 2.1796x; 1.7567x over previous
#include <cuda_runtime.h>

#define HID 128
#define LAT 256
#define NN  1024
#define GRID 136u

// ---------------- scratch (no allocations allowed) ----------------
__device__ float d_h   [LAT];            // latent hidden pre-LN
__device__ float d_g   [HID];            // global feature g
__device__ float d_gvec[HID];            // nr_b1 + g @ nr_w1[:,128:]^T
__device__ float d_w1hT[HID * HID];      // [c][k] = nr_w1[k][c]
__device__ float d_w2T [HID * HID];      // [k][j] = nr_w2[j][k]
__device__ float d_WaT [HID * HID];      // [k][j] = em_w1[j][k]
__device__ float d_WbT [HID * HID];      // [k][j] = em_w1[j][128+k]
__device__ float d_piT [HID * NN];       // [h][i] = pi[i][h]
__device__ float d_pbT [HID * NN];       // [h][j] = pj[j][h] + em_b1[h]

__device__ unsigned d_bar_count = 0;
__device__ unsigned d_bar_gen   = 0;

__device__ __forceinline__ unsigned ldcg_u32(const unsigned* p) {
    unsigned v;
    asm volatile("ld.global.cg.u32 %0, [%1];" : "=r"(v) : "l"(p));
    return v;
}

// software grid barrier: all GRID blocks resident (GRID <= #SMs)
__device__ __forceinline__ void grid_bar() {
    __syncthreads();
    if (threadIdx.x == 0) {
        unsigned g = ldcg_u32(&d_bar_gen);
        __threadfence();                      // release prior writes
        if (atomicAdd(&d_bar_count, 1u) == GRID - 1u) {
            d_bar_count = 0;
            __threadfence();
            atomicAdd(&d_bar_gen, 1u);        // release
        } else {
            while (ldcg_u32(&d_bar_gen) == g) {}
        }
        __threadfence();                      // acquire
    }
    __syncthreads();
}

__device__ __forceinline__ float warp_sum(float v) {
#pragma unroll
    for (int o = 16; o; o >>= 1) v += __shfl_xor_sync(0xffffffffu, v, o);
    return v;
}

__device__ __forceinline__ float2 f2add(float2 a, float2 b) {
    unsigned long long ua = *reinterpret_cast<unsigned long long*>(&a);
    unsigned long long ub = *reinterpret_cast<unsigned long long*>(&b);
    unsigned long long ur;
    asm("add.rn.f32x2 %0, %1, %2;" : "=l"(ur) : "l"(ua), "l"(ub));
    return *reinterpret_cast<float2*>(&ur);
}
__device__ __forceinline__ float2 f2fma(float2 a, float2 b, float2 c) {
    unsigned long long ua = *reinterpret_cast<unsigned long long*>(&a);
    unsigned long long ub = *reinterpret_cast<unsigned long long*>(&b);
    unsigned long long uc = *reinterpret_cast<unsigned long long*>(&c);
    unsigned long long ur;
    asm("fma.rn.f32x2 %0, %1, %2, %3;" : "=l"(ur) : "l"(ua), "l"(ub), "l"(uc));
    return *reinterpret_cast<float2*>(&ur);
}
__device__ __forceinline__ float sigm(float x) { return 1.f / (1.f + __expf(-x)); }

// ---------------- the fused kernel ----------------
__global__ __launch_bounds__(256) void kFused(
    const float* __restrict__ z,  const float* __restrict__ ne,
    const float* __restrict__ ld_w1, const float* __restrict__ ld_b1,
    const float* __restrict__ ld_g,  const float* __restrict__ ld_be,
    const float* __restrict__ ld_w2, const float* __restrict__ ld_b2,
    const float* __restrict__ nr_w1, const float* __restrict__ nr_b1,
    const float* __restrict__ nr_g,  const float* __restrict__ nr_be,
    const float* __restrict__ nr_w2, const float* __restrict__ nr_b2,
    const float* __restrict__ em_w1, const float* __restrict__ em_b1,
    const float* __restrict__ em_w2, const float* __restrict__ em_b2,
    float* __restrict__ out)
{
    __shared__ float SM[8448];   // 33 KB, re-purposed per phase
    const int t   = threadIdx.x;
    const int blk = blockIdx.x;
    const int w = t >> 5, l = t & 31;

    // ================= phase 0: h GEMV (blocks 0..63) + transposes (64..127) =================
    if (blk < 64) {
        float* z_s  = SM;            // 256
        float* part = SM + 256;      // 8
        if (t < 64) ((float4*)z_s)[t] = ((const float4*)z)[t];
        __syncthreads();
        const int row  = blk * 4 + (w >> 1);
        const int half = w & 1;
        const float4* wr = (const float4*)&ld_w1[row * LAT + half * 128];
        float4 A  = wr[l];
        float4 zv = ((const float4*)z_s)[half * 32 + l];
        float p = A.x*zv.x + A.y*zv.y + A.z*zv.z + A.w*zv.w;
        p = warp_sum(p);
        if (l == 0) part[w] = p;
        __syncthreads();
        if (t < 4) {
            int r = blk * 4 + t;
            d_h[r] = part[2*t] + part[2*t + 1] + ld_b1[r];
        }
    } else if (blk < 128) {
        float (*s)[33] = (float(*)[33])SM;
        const int tileIdx = blk - 64;              // 0..63
        const int m  = tileIdx >> 4;
        const int t16 = tileIdx & 15;
        const int c0 = (t16 >> 2) * 32;
        const int k0 = (t16 & 3) * 32;
        const float* src; int stride, colOff; float* dst;
        if      (m == 0) { src = nr_w1; stride = LAT; colOff = 0;   dst = d_w1hT; }
        else if (m == 1) { src = nr_w2; stride = HID; colOff = 0;   dst = d_w2T;  }
        else if (m == 2) { src = em_w1; stride = LAT; colOff = 0;   dst = d_WaT;  }
        else             { src = em_w1; stride = LAT; colOff = HID; dst = d_WbT;  }
        const int x = t & 31, y = t >> 5;
#pragma unroll
        for (int yy = y; yy < 32; yy += 8)
            s[yy][x] = src[(k0 + yy) * stride + colOff + c0 + x];
        __syncthreads();
#pragma unroll
        for (int yy = y; yy < 32; yy += 8)
            dst[(c0 + yy) * HID + k0 + x] = s[x][yy];
    }
    grid_bar();

    // ================= phase 1: g[blk] = relu(LN(h)) . ld_w2[blk] + b2  (blocks 0..127) =================
    if (blk < 128) {
        float* h_s  = SM;            // 256
        float* a_s  = SM + 256;      // 256
        float* redA = SM + 512;      // 8
        float* redB = SM + 520;      // 8
        float* part = SM + 528;      // 8
        if (t < 64) ((float4*)h_s)[t] = ((const float4*)d_h)[t];
        __syncthreads();
        float x = h_s[t];
        float s1 = warp_sum(x), s2 = warp_sum(x * x);
        if (l == 0) { redA[w] = s1; redB[w] = s2; }
        __syncthreads();
        float tot = 0.f, tot2 = 0.f;
#pragma unroll
        for (int i = 0; i < 8; i++) { tot += redA[i]; tot2 += redB[i]; }
        float mu = tot * (1.f / 256.f);
        float var = tot2 * (1.f / 256.f) - mu * mu;
        float rs = rsqrtf(var + 1e-5f);
        a_s[t] = fmaxf((x - mu) * rs * ld_g[t] + ld_be[t], 0.f);
        __syncthreads();
        float p = a_s[t] * ld_w2[blk * LAT + t];
        p = warp_sum(p);
        if (l == 0) part[w] = p;
        __syncthreads();
        if (t == 0) {
            float s = 0.f;
#pragma unroll
            for (int i = 0; i < 8; i++) s += part[i];
            d_g[blk] = s + ld_b2[blk];
        }
    }
    grid_bar();

    // ================= phase 2: gvec[blk] = nr_b1[blk] + g . nr_w1[blk][128:]  (blocks 0..127) =================
    if (blk < 128) {
        float* g_s  = SM;            // 128
        float* part = SM + 128;      // 8
        if (t < 128) g_s[t] = d_g[t];
        __syncthreads();
        float p = (t < 128) ? g_s[t] * nr_w1[blk * LAT + HID + t] : 0.f;
        p = warp_sum(p);
        if (l == 0) part[w] = p;
        __syncthreads();
        if (t == 0) {
            float s = 0.f;
#pragma unroll
            for (int i = 0; i < 8; i++) s += part[i];
            d_gvec[blk] = s + nr_b1[blk];
        }
    }
    grid_bar();

    // ================= phase 3: node MLP -> piT / pbT  (blocks 0..127, 8 nodes each) =================
    if (blk < 128) {
        float* ne_s = SM;            // 1024
        float* h_s  = SM + 1024;     // 1024
        float* nf_s = SM + 2048;     // 1024
        float* pis  = SM + 3072;     // 1024
        float* pbs  = SM + 4096;     // 1024
        const int i0 = blk * 8;
        const int r = t >> 5;
        const int j4 = l * 4;

        for (int q = t; q < 8 * HID; q += 256) ne_s[q] = ne[i0 * HID + q];
        __syncthreads();

        float a0 = d_gvec[j4], a1 = d_gvec[j4+1], a2 = d_gvec[j4+2], a3 = d_gvec[j4+3];
#pragma unroll 8
        for (int c = 0; c < HID; c++) {
            float nec = ne_s[r * HID + c];
            float4 wv = *(const float4*)&d_w1hT[c * HID + j4];
            a0 = fmaf(nec, wv.x, a0); a1 = fmaf(nec, wv.y, a1);
            a2 = fmaf(nec, wv.z, a2); a3 = fmaf(nec, wv.w, a3);
        }
        *(float4*)&h_s[r * HID + j4] = make_float4(a0, a1, a2, a3);
        __syncthreads();

        {
            float xs[4], s1 = 0.f, s2 = 0.f;
#pragma unroll
            for (int m = 0; m < 4; m++) {
                xs[m] = h_s[r * HID + l + 32 * m];
                s1 += xs[m]; s2 += xs[m] * xs[m];
            }
            s1 = warp_sum(s1); s2 = warp_sum(s2);
            float mu = s1 * (1.f / 128.f);
            float var = s2 * (1.f / 128.f) - mu * mu;
            float rs = rsqrtf(var + 1e-5f);
#pragma unroll
            for (int m = 0; m < 4; m++) {
                int c = l + 32 * m;
                h_s[r * HID + c] = fmaxf((xs[m] - mu) * rs * nr_g[c] + nr_be[c], 0.f);
            }
        }
        __syncthreads();

        float n0 = nr_b2[j4], n1 = nr_b2[j4+1], n2 = nr_b2[j4+2], n3 = nr_b2[j4+3];
#pragma unroll 8
        for (int c = 0; c < HID; c++) {
            float ac = h_s[r * HID + c];
            float4 wv = *(const float4*)&d_w2T[c * HID + j4];
            n0 = fmaf(ac, wv.x, n0); n1 = fmaf(ac, wv.y, n1);
            n2 = fmaf(ac, wv.z, n2); n3 = fmaf(ac, wv.w, n3);
        }
        *(float4*)&nf_s[r * HID + j4] = make_float4(n0, n1, n2, n3);
        __syncthreads();

        float p0 = 0.f, p1 = 0.f, p2 = 0.f, p3 = 0.f;
        float q0 = em_b1[j4], q1 = em_b1[j4+1], q2 = em_b1[j4+2], q3 = em_b1[j4+3];
#pragma unroll 4
        for (int c = 0; c < HID; c++) {
            float nfc = nf_s[r * HID + c];
            float4 wa = *(const float4*)&d_WaT[c * HID + j4];
            float4 wb = *(const float4*)&d_WbT[c * HID + j4];
            p0 = fmaf(nfc, wa.x, p0); p1 = fmaf(nfc, wa.y, p1);
            p2 = fmaf(nfc, wa.z, p2); p3 = fmaf(nfc, wa.w, p3);
            q0 = fmaf(nfc, wb.x, q0); q1 = fmaf(nfc, wb.y, q1);
            q2 = fmaf(nfc, wb.z, q2); q3 = fmaf(nfc, wb.w, q3);
        }
        *(float4*)&pis[r * HID + j4] = make_float4(p0, p1, p2, p3);
        *(float4*)&pbs[r * HID + j4] = make_float4(q0, q1, q2, q3);
        __syncthreads();

        if (t < HID) {
            const int j = t;
            float4 lo = make_float4(pis[0*HID+j], pis[1*HID+j], pis[2*HID+j], pis[3*HID+j]);
            float4 hi = make_float4(pis[4*HID+j], pis[5*HID+j], pis[6*HID+j], pis[7*HID+j]);
            *(float4*)&d_piT[j * NN + i0]     = lo;
            *(float4*)&d_piT[j * NN + i0 + 4] = hi;
            float4 lo2 = make_float4(pbs[0*HID+j], pbs[1*HID+j], pbs[2*HID+j], pbs[3*HID+j]);
            float4 hi2 = make_float4(pbs[4*HID+j], pbs[5*HID+j], pbs[6*HID+j], pbs[7*HID+j]);
            *(float4*)&d_pbT[j * NN + i0]     = lo2;
            *(float4*)&d_pbT[j * NN + i0 + 4] = hi2;
        }
    }
    grid_bar();

    // ================= phase 4: edge scores + fused symmetrize (all 136 blocks) =================
    {
        float* pool = SM;                 // 8192 floats
        float* w_s  = SM + 8192;          // 128
        float (*piI)[64] = (float(*)[64])(pool);
        float (*pbJ)[64] = (float(*)[64])(pool + 2048);
        float (*piJ)[64] = (float(*)[64])(pool + 4096);
        float (*pbI)[64] = (float(*)[64])(pool + 6144);

        const int tx = t & 15, ty = t >> 4;
        const int ty4 = ty * 4, tx4 = tx * 4;

        int b = blk, bi = 0;
        while (b >= (16 - bi)) { b -= (16 - bi); bi++; }
        const int bj = bi + b;
        const int i0 = bi * 64, j0 = bj * 64;

        if (t < HID) w_s[t] = em_w2[t];

        float2 acc1[4][2] = {};
        float2 acc2[4][2] = {};

#pragma unroll
        for (int ch = 0; ch < 4; ch++) {
            __syncthreads();
            const int h0 = ch * 32;
#pragma unroll
            for (int q = t; q < 32 * 16; q += 256) {
                int hl = q >> 4, c4 = (q & 15) * 4;
                *(float4*)&piI[hl][c4] = *(const float4*)&d_piT[(h0 + hl) * NN + i0 + c4];
                *(float4*)&pbJ[hl][c4] = *(const float4*)&d_pbT[(h0 + hl) * NN + j0 + c4];
                *(float4*)&piJ[hl][c4] = *(const float4*)&d_piT[(h0 + hl) * NN + j0 + c4];
                *(float4*)&pbI[hl][c4] = *(const float4*)&d_pbT[(h0 + hl) * NN + i0 + c4];
            }
            __syncthreads();

#pragma unroll 8
            for (int hl = 0; hl < 32; hl++) {
                float4 pI = *(const float4*)&piI[hl][ty4];
                float4 bI = *(const float4*)&pbI[hl][ty4];
                float4 pJ = *(const float4*)&piJ[hl][tx4];
                float4 bJ = *(const float4*)&pbJ[hl][tx4];
                float wh = w_s[h0 + hl];
                float2 w2 = make_float2(wh, wh);
                float2 qq0 = make_float2(bJ.x, bJ.y), qq1 = make_float2(bJ.z, bJ.w);
                float2 rr0 = make_float2(pJ.x, pJ.y), rr1 = make_float2(pJ.z, pJ.w);
                float pa[4] = {pI.x, pI.y, pI.z, pI.w};
                float ba[4] = {bI.x, bI.y, bI.z, bI.w};
#pragma unroll
                for (int a = 0; a < 4; a++) {
                    float2 pp = make_float2(pa[a], pa[a]);
                    float2 s0 = f2add(pp, qq0);
                    s0.x = fmaxf(s0.x, 0.f); s0.y = fmaxf(s0.y, 0.f);
                    acc1[a][0] = f2fma(s0, w2, acc1[a][0]);
                    float2 s1 = f2add(pp, qq1);
                    s1.x = fmaxf(s1.x, 0.f); s1.y = fmaxf(s1.y, 0.f);
                    acc1[a][1] = f2fma(s1, w2, acc1[a][1]);

                    float2 bb = make_float2(ba[a], ba[a]);
                    float2 t0 = f2add(bb, rr0);
                    t0.x = fmaxf(t0.x, 0.f); t0.y = fmaxf(t0.y, 0.f);
                    acc2[a][0] = f2fma(t0, w2, acc2[a][0]);
                    float2 t1 = f2add(bb, rr1);
                    t1.x = fmaxf(t1.x, 0.f); t1.y = fmaxf(t1.y, 0.f);
                    acc2[a][1] = f2fma(t1, w2, acc2[a][1]);
                }
            }
        }

        const float b2 = em_b2[0];
        __syncthreads();
        float (*ov)[65] = (float(*)[65])pool;   // 64*65 = 4160 floats

#pragma unroll
        for (int a = 0; a < 4; a++) {
            float v0 = 0.5f * (sigm(acc1[a][0].x + b2) + sigm(acc2[a][0].x + b2));
            float v1 = 0.5f * (sigm(acc1[a][0].y + b2) + sigm(acc2[a][0].y + b2));
            float v2 = 0.5f * (sigm(acc1[a][1].x + b2) + sigm(acc2[a][1].x + b2));
            float v3 = 0.5f * (sigm(acc1[a][1].y + b2) + sigm(acc2[a][1].y + b2));
            *(float4*)&out[(i0 + ty4 + a) * NN + j0 + tx4] = make_float4(v0, v1, v2, v3);
            ov[ty4 + a][tx4]     = v0;
            ov[ty4 + a][tx4 + 1] = v1;
            ov[ty4 + a][tx4 + 2] = v2;
            ov[ty4 + a][tx4 + 3] = v3;
        }
        __syncthreads();

#pragma unroll
        for (int rb = 0; rb < 4; rb++) {
            int r = rb * 16 + ty;
            int c4 = tx4;
            float4 v = make_float4(ov[c4][r], ov[c4+1][r], ov[c4+2][r], ov[c4+3][r]);
            *(float4*)&out[(j0 + r) * NN + i0 + c4] = v;
        }
    }
}

// ---------------- launch ----------------
extern "C" void kernel_launch(void* const* d_in, const int* in_sizes, int n_in,
                              void* d_out, int out_size)
{
    const int o = (n_in >= 19 && in_sizes[2] == 1) ? 1 : 0;
    const float* z     = (const float*)d_in[0];
    const float* ne    = (const float*)d_in[1];
    const float* ld_w1 = (const float*)d_in[2 + o];
    const float* ld_b1 = (const float*)d_in[3 + o];
    const float* ld_g  = (const float*)d_in[4 + o];
    const float* ld_be = (const float*)d_in[5 + o];
    const float* ld_w2 = (const float*)d_in[6 + o];
    const float* ld_b2 = (const float*)d_in[7 + o];
    const float* nr_w1 = (const float*)d_in[8 + o];
    const float* nr_b1 = (const float*)d_in[9 + o];
    const float* nr_g  = (const float*)d_in[10 + o];
    const float* nr_be = (const float*)d_in[11 + o];
    const float* nr_w2 = (const float*)d_in[12 + o];
    const float* nr_b2 = (const float*)d_in[13 + o];
    const float* em_w1 = (const float*)d_in[14 + o];
    const float* em_b1 = (const float*)d_in[15 + o];
    const float* em_w2 = (const float*)d_in[16 + o];
    const float* em_b2 = (const float*)d_in[17 + o];
    float* out = (float*)d_out;

    kFused<<<GRID, 256>>>(z, ne, ld_w1, ld_b1, ld_g, ld_be, ld_w2, ld_b2,
                          nr_w1, nr_b1, nr_g, nr_be, nr_w2, nr_b2,
                          em_w1, em_b1, em_w2, em_b2, out);
}

// round 5
// speedup vs baseline: 2.2827x; 1.0473x over previous
#include <cuda_runtime.h>

#define HID 128
#define LAT 256
#define NN  1024
#define GRID 136u
#define NT   512

// ---------------- scratch (no allocations allowed) ----------------
__device__ float d_h   [LAT];
__device__ float d_g   [HID];
__device__ float d_gvec[HID];
__device__ float d_w1hT[HID * HID];
__device__ float d_w2T [HID * HID];
__device__ float d_WaT [HID * HID];
__device__ float d_WbT [HID * HID];
__device__ float d_piT [HID * NN];
__device__ float d_pbT [HID * NN];

__device__ unsigned d_bar_count = 0;
__device__ unsigned d_bar_gen   = 0;

__device__ __forceinline__ unsigned ldcg_u32(const unsigned* p) {
    unsigned v;
    asm volatile("ld.global.cg.u32 %0, [%1];" : "=r"(v) : "l"(p));
    return v;
}

// software grid barrier: all GRID blocks resident (GRID <= #SMs).
// ALL threads fence before (release own writes) and after (acquire).
__device__ __forceinline__ void grid_bar() {
    __syncthreads();
    __threadfence();                          // every thread releases its writes
    __syncthreads();
    if (threadIdx.x == 0) {
        unsigned g = ldcg_u32(&d_bar_gen);
        if (atomicAdd(&d_bar_count, 1u) == GRID - 1u) {
            d_bar_count = 0;
            __threadfence();
            atomicAdd(&d_bar_gen, 1u);
        } else {
            while (ldcg_u32(&d_bar_gen) == g) {}
        }
    }
    __syncthreads();
    __threadfence();                          // every thread acquires
}

__device__ __forceinline__ float warp_sum(float v) {
#pragma unroll
    for (int o = 16; o; o >>= 1) v += __shfl_xor_sync(0xffffffffu, v, o);
    return v;
}

__device__ __forceinline__ float2 f2add(float2 a, float2 b) {
    unsigned long long ua = *reinterpret_cast<unsigned long long*>(&a);
    unsigned long long ub = *reinterpret_cast<unsigned long long*>(&b);
    unsigned long long ur;
    asm("add.rn.f32x2 %0, %1, %2;" : "=l"(ur) : "l"(ua), "l"(ub));
    return *reinterpret_cast<float2*>(&ur);
}
__device__ __forceinline__ float2 f2fma(float2 a, float2 b, float2 c) {
    unsigned long long ua = *reinterpret_cast<unsigned long long*>(&a);
    unsigned long long ub = *reinterpret_cast<unsigned long long*>(&b);
    unsigned long long uc = *reinterpret_cast<unsigned long long*>(&c);
    unsigned long long ur;
    asm("fma.rn.f32x2 %0, %1, %2, %3;" : "=l"(ur) : "l"(ua), "l"(ub), "l"(uc));
    return *reinterpret_cast<float2*>(&ur);
}
__device__ __forceinline__ float sigm(float x) { return 1.f / (1.f + __expf(-x)); }

// ---------------- the fused kernel ----------------
__global__ __launch_bounds__(NT) void kFused(
    const float* __restrict__ z,  const float* __restrict__ ne,
    const float* __restrict__ ld_w1, const float* __restrict__ ld_b1,
    const float* __restrict__ ld_g,  const float* __restrict__ ld_be,
    const float* __restrict__ ld_w2, const float* __restrict__ ld_b2,
    const float* __restrict__ nr_w1, const float* __restrict__ nr_b1,
    const float* __restrict__ nr_g,  const float* __restrict__ nr_be,
    const float* __restrict__ nr_w2, const float* __restrict__ nr_b2,
    const float* __restrict__ em_w1, const float* __restrict__ em_b1,
    const float* __restrict__ em_w2, const float* __restrict__ em_b2,
    float* __restrict__ out)
{
    __shared__ float SM[8448];   // 33 KB, re-purposed per phase
    const int t   = threadIdx.x;
    const int blk = blockIdx.x;
    const int w = t >> 5, l = t & 31;

    // ===== phase 0: h GEMV (blocks 0..31, 8 rows each) + transposes (64..127) =====
    if (blk < 32) {
        float* z_s  = SM;            // 256
        float* part = SM + 256;      // 16
        if (t < 64) ((float4*)z_s)[t] = ((const float4*)z)[t];
        __syncthreads();
        const int row  = blk * 8 + (w >> 1);
        const int half = w & 1;
        float4 A  = ((const float4*)&ld_w1[row * LAT + half * 128])[l];
        float4 zv = ((const float4*)z_s)[half * 32 + l];
        float p = A.x*zv.x + A.y*zv.y + A.z*zv.z + A.w*zv.w;
        p = warp_sum(p);
        if (l == 0) part[w] = p;
        __syncthreads();
        if (t < 8) {
            int r = blk * 8 + t;
            d_h[r] = part[2*t] + part[2*t + 1] + ld_b1[r];
        }
    } else if (blk >= 64 && blk < 128) {
        float (*s)[33] = (float(*)[33])SM;
        const int tileIdx = blk - 64;
        const int m  = tileIdx >> 4;
        const int t16 = tileIdx & 15;
        const int c0 = (t16 >> 2) * 32;
        const int k0 = (t16 & 3) * 32;
        const float* src; int stride, colOff; float* dst;
        if      (m == 0) { src = nr_w1; stride = LAT; colOff = 0;   dst = d_w1hT; }
        else if (m == 1) { src = nr_w2; stride = HID; colOff = 0;   dst = d_w2T;  }
        else if (m == 2) { src = em_w1; stride = LAT; colOff = 0;   dst = d_WaT;  }
        else             { src = em_w1; stride = LAT; colOff = HID; dst = d_WbT;  }
        const int x = t & 31, y = t >> 5;
#pragma unroll
        for (int yy = y; yy < 32; yy += 16)
            s[yy][x] = src[(k0 + yy) * stride + colOff + c0 + x];
        __syncthreads();
#pragma unroll
        for (int yy = y; yy < 32; yy += 16)
            dst[(c0 + yy) * HID + k0 + x] = s[x][yy];
    }
    grid_bar();

    // ===== phase 1: g[blk] = relu(LN(h)) . ld_w2[blk] + b2  (blocks 0..127) =====
    if (blk < 128) {
        float* h_s  = SM;            // 256
        float* a_s  = SM + 256;      // 256
        float* redA = SM + 512;      // 8
        float* redB = SM + 520;      // 8
        float* part = SM + 528;      // 8
        if (t < 64) ((float4*)h_s)[t] = ((const float4*)d_h)[t];
        __syncthreads();
        float x = (t < 256) ? h_s[t] : 0.f;
        float s1 = warp_sum(x), s2 = warp_sum(x * x);
        if (l == 0 && w < 8) { redA[w] = s1; redB[w] = s2; }
        __syncthreads();
        float tot = 0.f, tot2 = 0.f;
#pragma unroll
        for (int i = 0; i < 8; i++) { tot += redA[i]; tot2 += redB[i]; }
        float mu = tot * (1.f / 256.f);
        float var = tot2 * (1.f / 256.f) - mu * mu;
        float rs = rsqrtf(var + 1e-5f);
        if (t < 256) a_s[t] = fmaxf((x - mu) * rs * ld_g[t] + ld_be[t], 0.f);
        __syncthreads();
        float p = (t < 256) ? a_s[t] * ld_w2[blk * LAT + t] : 0.f;
        p = warp_sum(p);
        if (l == 0 && w < 8) part[w] = p;
        __syncthreads();
        if (t == 0) {
            float s = 0.f;
#pragma unroll
            for (int i = 0; i < 8; i++) s += part[i];
            d_g[blk] = s + ld_b2[blk];
        }
    }
    grid_bar();

    // ===== phase 2: gvec[blk] = nr_b1[blk] + g . nr_w1[blk][128:]  (blocks 0..127) =====
    if (blk < 128) {
        float* g_s  = SM;            // 128
        float* part = SM + 128;      // 4
        if (t < 128) g_s[t] = d_g[t];
        __syncthreads();
        float p = (t < 128) ? g_s[t] * nr_w1[blk * LAT + HID + t] : 0.f;
        p = warp_sum(p);
        if (l == 0 && w < 4) part[w] = p;
        __syncthreads();
        if (t == 0) {
            float s = part[0] + part[1] + part[2] + part[3];
            d_gvec[blk] = s + nr_b1[blk];
        }
    }
    grid_bar();

    // ===== phase 3: node MLP -> piT / pbT  (blocks 0..127, 8 nodes, 64 thr/node) =====
    if (blk < 128) {
        float* ne_s = SM;            // 1024
        float* h_s  = SM + 1024;     // 1024
        float* nf_s = SM + 2048;     // 1024
        float* pis  = SM + 3072;     // 1024
        float* pbs  = SM + 4096;     // 1024
        float* red1 = SM + 5120;     // 16
        float* red2 = SM + 5136;     // 16
        const int i0 = blk * 8;
        const int r  = t >> 6;       // node 0..7
        const int u  = t & 63;
        const int j2 = u * 2;
        const int wh2 = u >> 5;      // which warp-half of the 64-thread group

        for (int q = t; q < 8 * HID; q += NT) ne_s[q] = ne[i0 * HID + q];
        __syncthreads();

        // h1 = ne_i @ w1h^T + gvec   (2 outputs/thread, packed fma)
        float2 acc = *(const float2*)&d_gvec[j2];
#pragma unroll 8
        for (int c = 0; c < HID; c++) {
            float nec = ne_s[r * HID + c];
            float2 wv = *(const float2*)&d_w1hT[c * HID + j2];
            acc = f2fma(make_float2(nec, nec), wv, acc);
        }
        *(float2*)&h_s[r * HID + j2] = acc;
        __syncthreads();

        // LayerNorm(128) + relu across the 64-thread group
        {
            float x0 = h_s[r * HID + u], x1 = h_s[r * HID + u + 64];
            float s1 = warp_sum(x0 + x1);
            float s2 = warp_sum(x0 * x0 + x1 * x1);
            if (l == 0) { red1[r * 2 + wh2] = s1; red2[r * 2 + wh2] = s2; }
            __syncthreads();
            float mu  = (red1[r * 2] + red1[r * 2 + 1]) * (1.f / 128.f);
            float var = (red2[r * 2] + red2[r * 2 + 1]) * (1.f / 128.f) - mu * mu;
            float rs = rsqrtf(var + 1e-5f);
            h_s[r * HID + u]      = fmaxf((x0 - mu) * rs * nr_g[u]      + nr_be[u],      0.f);
            h_s[r * HID + u + 64] = fmaxf((x1 - mu) * rs * nr_g[u + 64] + nr_be[u + 64], 0.f);
        }
        __syncthreads();

        // nf = a @ nr_w2^T + b2
        float2 nf = *(const float2*)&nr_b2[j2];
#pragma unroll 8
        for (int c = 0; c < HID; c++) {
            float ac = h_s[r * HID + c];
            float2 wv = *(const float2*)&d_w2T[c * HID + j2];
            nf = f2fma(make_float2(ac, ac), wv, nf);
        }
        *(float2*)&nf_s[r * HID + j2] = nf;
        __syncthreads();

        // pi = nf @ Wa^T ; pb = nf @ Wb^T + em_b1
        float2 pi = make_float2(0.f, 0.f);
        float2 pb = *(const float2*)&em_b1[j2];
#pragma unroll 4
        for (int c = 0; c < HID; c++) {
            float nfc = nf_s[r * HID + c];
            float2 wa = *(const float2*)&d_WaT[c * HID + j2];
            float2 wb = *(const float2*)&d_WbT[c * HID + j2];
            float2 nn = make_float2(nfc, nfc);
            pi = f2fma(nn, wa, pi);
            pb = f2fma(nn, wb, pb);
        }
        *(float2*)&pis[r * HID + j2] = pi;
        *(float2*)&pbs[r * HID + j2] = pb;
        __syncthreads();

        if (t < HID) {
            const int j = t;
            float4 lo = make_float4(pis[0*HID+j], pis[1*HID+j], pis[2*HID+j], pis[3*HID+j]);
            float4 hi = make_float4(pis[4*HID+j], pis[5*HID+j], pis[6*HID+j], pis[7*HID+j]);
            *(float4*)&d_piT[j * NN + i0]     = lo;
            *(float4*)&d_piT[j * NN + i0 + 4] = hi;
            float4 lo2 = make_float4(pbs[0*HID+j], pbs[1*HID+j], pbs[2*HID+j], pbs[3*HID+j]);
            float4 hi2 = make_float4(pbs[4*HID+j], pbs[5*HID+j], pbs[6*HID+j], pbs[7*HID+j]);
            *(float4*)&d_pbT[j * NN + i0]     = lo2;
            *(float4*)&d_pbT[j * NN + i0 + 4] = hi2;
        }
    }
    grid_bar();

    // ===== phase 4: edge scores + fused symmetrize (all 136 blocks, 512 thr) =====
    {
        float* pool = SM;                 // 8192 floats
        float* w_s  = SM + 8192;          // 128
        float (*piI)[64] = (float(*)[64])(pool);
        float (*pbJ)[64] = (float(*)[64])(pool + 2048);
        float (*piJ)[64] = (float(*)[64])(pool + 4096);
        float (*pbI)[64] = (float(*)[64])(pool + 6144);

        const int tx = t & 31;            // j-pair: j = 2*tx .. 2*tx+1
        const int ty = t >> 5;            // 0..15:  i = ty*4 + a
        const int ty4 = ty * 4;

        int b = blk, bi = 0;
        while (b >= (16 - bi)) { b -= (16 - bi); bi++; }
        const int bj = bi + b;
        const int i0 = bi * 64, j0 = bj * 64;

        if (t < HID) w_s[t] = em_w2[t];

        float2 acc1[4] = {};   // tile (I,J): i = ty4+a, j = 2tx..+1
        float2 acc2[4] = {};   // tile (J,I) transposed-staged: same (i,j) coords

#pragma unroll
        for (int ch = 0; ch < 4; ch++) {
            __syncthreads();
            const int h0 = ch * 32;
            {   // 512 float4 loads per tile-set, one per thread
                int hl = t >> 4, c4 = (t & 15) * 4;
                *(float4*)&piI[hl][c4] = *(const float4*)&d_piT[(h0 + hl) * NN + i0 + c4];
                *(float4*)&pbJ[hl][c4] = *(const float4*)&d_pbT[(h0 + hl) * NN + j0 + c4];
                *(float4*)&piJ[hl][c4] = *(const float4*)&d_piT[(h0 + hl) * NN + j0 + c4];
                *(float4*)&pbI[hl][c4] = *(const float4*)&d_pbT[(h0 + hl) * NN + i0 + c4];
            }
            __syncthreads();

#pragma unroll 8
            for (int hl = 0; hl < 32; hl++) {
                float4 pI = *(const float4*)&piI[hl][ty4];      // broadcast in warp
                float4 bI = *(const float4*)&pbI[hl][ty4];      // broadcast in warp
                float2 pJ = *(const float2*)&piJ[hl][tx * 2];
                float2 bJ = *(const float2*)&pbJ[hl][tx * 2];
                float wh = w_s[h0 + hl];
                float2 w2 = make_float2(wh, wh);
                float pa[4] = {pI.x, pI.y, pI.z, pI.w};
                float ba[4] = {bI.x, bI.y, bI.z, bI.w};
#pragma unroll
                for (int a = 0; a < 4; a++) {
                    float2 s = f2add(make_float2(pa[a], pa[a]), bJ);
                    s.x = fmaxf(s.x, 0.f); s.y = fmaxf(s.y, 0.f);
                    acc1[a] = f2fma(s, w2, acc1[a]);
                    float2 u2 = f2add(make_float2(ba[a], ba[a]), pJ);
                    u2.x = fmaxf(u2.x, 0.f); u2.y = fmaxf(u2.y, 0.f);
                    acc2[a] = f2fma(u2, w2, acc2[a]);
                }
            }
        }

        const float b2 = em_b2[0];
        __syncthreads();
        // staging buffer [j][i], row stride 68 (multiple of 4 -> float4-aligned rows)
        float (*ov)[68] = (float(*)[68])pool;   // 64*68 = 4352 floats <= 8448

#pragma unroll
        for (int a = 0; a < 4; a++) {
            float v0 = 0.5f * (sigm(acc1[a].x + b2) + sigm(acc2[a].x + b2));
            float v1 = 0.5f * (sigm(acc1[a].y + b2) + sigm(acc2[a].y + b2));
            *(float2*)&out[(i0 + ty4 + a) * NN + j0 + tx * 2] = make_float2(v0, v1);
            ov[tx * 2][ty4 + a]     = v0;
            ov[tx * 2 + 1][ty4 + a] = v1;
        }
        __syncthreads();

        // transposed write: out[(j0+r)][i0+c] = ov[r][c], 8 floats/thread
        {
            int r = t >> 3, c8 = (t & 7) * 8;
            float4 v0 = *(const float4*)&ov[r][c8];
            float4 v1 = *(const float4*)&ov[r][c8 + 4];
            *(float4*)&out[(j0 + r) * NN + i0 + c8]     = v0;
            *(float4*)&out[(j0 + r) * NN + i0 + c8 + 4] = v1;
        }
    }
}

// ---------------- launch ----------------
extern "C" void kernel_launch(void* const* d_in, const int* in_sizes, int n_in,
                              void* d_out, int out_size)
{
    const int o = (n_in >= 19 && in_sizes[2] == 1) ? 1 : 0;
    const float* z     = (const float*)d_in[0];
    const float* ne    = (const float*)d_in[1];
    const float* ld_w1 = (const float*)d_in[2 + o];
    const float* ld_b1 = (const float*)d_in[3 + o];
    const float* ld_g  = (const float*)d_in[4 + o];
    const float* ld_be = (const float*)d_in[5 + o];
    const float* ld_w2 = (const float*)d_in[6 + o];
    const float* ld_b2 = (const float*)d_in[7 + o];
    const float* nr_w1 = (const float*)d_in[8 + o];
    const float* nr_b1 = (const float*)d_in[9 + o];
    const float* nr_g  = (const float*)d_in[10 + o];
    const float* nr_be = (const float*)d_in[11 + o];
    const float* nr_w2 = (const float*)d_in[12 + o];
    const float* nr_b2 = (const float*)d_in[13 + o];
    const float* em_w1 = (const float*)d_in[14 + o];
    const float* em_b1 = (const float*)d_in[15 + o];
    const float* em_w2 = (const float*)d_in[16 + o];
    const float* em_b2 = (const float*)d_in[17 + o];
    float* out = (float*)d_out;

    kFused<<<GRID, NT>>>(z, ne, ld_w1, ld_b1, ld_g, ld_be, ld_w2, ld_b2,
                         nr_w1, nr_b1, nr_g, nr_be, nr_w2, nr_b2,
                         em_w1, em_b1, em_w2, em_b2, out);
}